// round 11
// baseline (speedup 1.0000x reference)
#include <cuda_runtime.h>
#include <math.h>

#define HH 512
#define WW 1024
#define BATCH 4
#define BW 32
#define TH 8     // pixel tile height per block
#define TY 4     // thread rows (2 pixels each)
#define NRP ((TH + 2) / 2)   // padded row-pairs = 5

typedef unsigned long long ull;

// ---------------- packed f32x2 primitives (sm_103a) ----------------
__device__ __forceinline__ ull pack2(float lo, float hi) {
    ull v;
    asm("mov.b64 %0, {%1, %2};" : "=l"(v)
        : "r"(__float_as_uint(lo)), "r"(__float_as_uint(hi)));
    return v;
}
__device__ __forceinline__ void unpack2(ull v, float& lo, float& hi) {
    unsigned a, b;
    asm("mov.b64 {%0, %1}, %2;" : "=r"(a), "=r"(b) : "l"(v));
    lo = __uint_as_float(a);
    hi = __uint_as_float(b);
}
// (a.lane1, b.lane0) register splice — the vertical-window funnel
__device__ __forceinline__ ull funnel2(ull a, ull b) {
    ull r;
    asm("{\n\t"
        ".reg .b32 al, ah, bl, bh;\n\t"
        "mov.b64 {al, ah}, %1;\n\t"
        "mov.b64 {bl, bh}, %2;\n\t"
        "mov.b64 %0, {ah, bl};\n\t"
        "}" : "=l"(r) : "l"(a), "l"(b));
    return r;
}
__device__ __forceinline__ ull add2(ull a, ull b) {
    ull d; asm("add.rn.f32x2 %0, %1, %2;" : "=l"(d) : "l"(a), "l"(b)); return d;
}
__device__ __forceinline__ ull sub2(ull a, ull b) {
    ull d; asm("sub.rn.f32x2 %0, %1, %2;" : "=l"(d) : "l"(a), "l"(b)); return d;
}
__device__ __forceinline__ ull mul2(ull a, ull b) {
    ull d; asm("mul.rn.f32x2 %0, %1, %2;" : "=l"(d) : "l"(a), "l"(b)); return d;
}
__device__ __forceinline__ ull fma2(ull a, ull b, ull c) {
    ull d; asm("fma.rn.f32x2 %0, %1, %2, %3;" : "=l"(d) : "l"(a), "l"(b), "l"(c)); return d;
}
__device__ __forceinline__ ull neg2(ull a) { return a ^ 0x8000000080000000ULL; }

struct dd2 { ull hi, lo; };

// sum of 3 packed products, exact per lane (TwoProd + TwoSum chain)
__device__ __forceinline__ dd2 sum3prod2(ull a0, ull b0, ull a1, ull b1,
                                         ull a2, ull b2) {
    ull p0 = mul2(a0, b0), e0 = fma2(a0, b0, neg2(p0));
    ull p1 = mul2(a1, b1), e1 = fma2(a1, b1, neg2(p1));
    ull p2 = mul2(a2, b2), e2 = fma2(a2, b2, neg2(p2));
    ull s  = add2(p0, p1);
    ull bb = sub2(s, p0);
    ull er1 = add2(sub2(p0, sub2(s, bb)), sub2(p1, bb));
    ull s2  = add2(s, p2);
    ull bb2 = sub2(s2, s);
    ull er2 = add2(sub2(s, sub2(s2, bb2)), sub2(p2, bb2));
    dd2 r;
    r.hi = s2;
    r.lo = add2(add2(add2(e0, e1), e2), add2(er1, er2));
    return r;
}
// exact packed dd + dd
__device__ __forceinline__ dd2 ddadd2(dd2 a, dd2 b) {
    ull s  = add2(a.hi, b.hi);
    ull bb = sub2(s, a.hi);
    ull er = add2(sub2(a.hi, sub2(s, bb)), sub2(b.hi, bb));
    dd2 r; r.hi = s; r.lo = add2(add2(a.lo, b.lo), er);
    return r;
}
// dd += packed plain value, exact
__device__ __forceinline__ dd2 ddaddf2(dd2 a, ull p) {
    ull s  = add2(a.hi, p);
    ull bb = sub2(s, a.hi);
    ull er = add2(sub2(a.hi, sub2(s, bb)), sub2(p, bb));
    dd2 r; r.hi = s; r.lo = add2(a.lo, er);
    return r;
}
// relaxed packed dd multiply (drops lo*lo)
__device__ __forceinline__ dd2 ddmul2(dd2 a, dd2 b) {
    ull p = mul2(a.hi, b.hi);
    ull e = fma2(a.hi, b.hi, neg2(p));
    e = fma2(a.hi, b.lo, e);
    e = fma2(a.lo, b.hi, e);
    dd2 r; r.hi = p; r.lo = e;
    return r;
}
// packed dd * packed plain
__device__ __forceinline__ dd2 ddmulf2(dd2 a, ull b) {
    ull p = mul2(a.hi, b);
    ull e = fma2(a.hi, b, neg2(p));
    e = fma2(a.lo, b, e);
    dd2 r; r.hi = p; r.lo = e;
    return r;
}
// packed cofactor a*b - c*d, exact hi-difference
__device__ __forceinline__ dd2 ddcof2(dd2 a, dd2 b, dd2 c, dd2 d) {
    dd2 p = ddmul2(a, b);
    dd2 q = ddmul2(c, d);
    ull s  = sub2(p.hi, q.hi);
    ull bb = sub2(s, p.hi);
    ull er = add2(sub2(p.hi, sub2(s, bb)), sub2(neg2(q.hi), bb));
    dd2 r; r.hi = s; r.lo = add2(er, sub2(p.lo, q.lo));
    return r;
}
// exact packed 3-sum of dd values
__device__ __forceinline__ dd2 sum3dd2(dd2 a, dd2 b, dd2 c) {
    ull s  = add2(a.hi, b.hi);
    ull bb = sub2(s, a.hi);
    ull er1 = add2(sub2(a.hi, sub2(s, bb)), sub2(b.hi, bb));
    ull s2  = add2(s, c.hi);
    ull bb2 = sub2(s2, s);
    ull er2 = add2(sub2(s, sub2(s2, bb2)), sub2(c.hi, bb2));
    dd2 r;
    r.hi = s2;
    r.lo = add2(add2(add2(a.lo, b.lo), c.lo), add2(er1, er2));
    return r;
}

// ---------------- ray tables (sin/cos in double, rounded to fp32) ----------
__device__ float g_st[WW];
__device__ float g_ct[WW];
__device__ float g_sp[HH];
__device__ float g_cp[HH];

__global__ void rays_kernel() {
    int t = blockIdx.x * blockDim.x + threadIdx.x;
    const float PI_F = 3.14159265358979323846f;   // fl32(pi)
    if (t < WW) {
        float jn = __fmul_rn((float)t + 0.5f, 1.0f / (float)WW);
        float th = __fsub_rn(__fmul_rn(jn, __fmul_rn(2.0f, PI_F)), PI_F);
        double thd = (double)th;
        g_st[t] = (float)sin(thd);
        g_ct[t] = (float)cos(thd);
    } else if (t < WW + HH) {
        int i = t - WW;
        float in_ = __fmul_rn((float)i + 0.5f, 1.0f / (float)HH);
        float ph = __fsub_rn(0.5f * PI_F, __fmul_rn(in_, PI_F));
        double phd = (double)ph;
        g_sp[i] = (float)sin(phd);
        g_cp[i] = (float)cos(phd);
    }
}

// Row-pair packing: lane0 = even padded row, lane1 = odd padded row.
// Quantities 0:xx 1:xy 2:xz 3:yy 4:yz 5:zz (dd); b quantities x,y,z (plain).
__global__ __launch_bounds__(BW * TY, 9)
void normals_kernel(const float* __restrict__ depth, float* __restrict__ out) {
    __shared__ float4 pts[TH + 2][BW + 2];
    __shared__ ulonglong2 HsD[6][NRP][BW];   // dd {hi2, lo2}, row-pair packed
    __shared__ ull HsB[3][NRP][BW];          // plain b sums, row-pair packed

    const int bb = blockIdx.z;
    const int i0 = blockIdx.y * TH;
    const int j0 = blockIdx.x * BW;
    const int tid = threadIdx.y * BW + threadIdx.x;
    const int NT = BW * TY;
    const float* dptr = depth + (size_t)bb * (HH * WW);

    // Phase A: (TH+2)x(BW+2) tile of fp32 3D points, zero-padded.
    for (int t = tid; t < (TH + 2) * (BW + 2); t += NT) {
        int ly = t / (BW + 2);
        int lx = t - ly * (BW + 2);
        int gi = i0 + ly - 1;
        int gj = j0 + lx - 1;
        float4 p = make_float4(0.0f, 0.0f, 0.0f, 0.0f);
        if (gi >= 0 && gi < HH && gj >= 0 && gj < WW) {
            float d  = __ldg(&dptr[(size_t)gi * WW + gj]);
            float st = g_st[gj];
            float ct = g_ct[gj];
            float sp = g_sp[gi];
            float cp = g_cp[gi];
            float x = __fmul_rn(cp, st);
            float z = __fmul_rn(cp, ct);
            p.x = __fmul_rn(d, x);
            p.y = __fmul_rn(d, sp);
            p.z = __fmul_rn(d, z);
        }
        pts[ly][lx] = p;
    }
    __syncthreads();

    // Phase B: exact horizontal 3-window sums for TWO rows at once
    // (row-pair packed lanes). 3 operand packs per column; 6 dd pipelines.
    for (int t = tid; t < NRP * BW; t += NT) {
        int k  = t / BW;            // row-pair index (padded rows 2k, 2k+1)
        int lx = t - k * BW;
        float4 q0 = pts[2 * k][lx];
        float4 q1 = pts[2 * k][lx + 1];
        float4 q2 = pts[2 * k][lx + 2];
        float4 r0 = pts[2 * k + 1][lx];
        float4 r1 = pts[2 * k + 1][lx + 1];
        float4 r2 = pts[2 * k + 1][lx + 2];

        ull px0 = pack2(q0.x, r0.x), py0 = pack2(q0.y, r0.y), pz0 = pack2(q0.z, r0.z);
        ull px1 = pack2(q1.x, r1.x), py1 = pack2(q1.y, r1.y), pz1 = pack2(q1.z, r1.z);
        ull px2 = pack2(q2.x, r2.x), py2 = pack2(q2.y, r2.y), pz2 = pack2(q2.z, r2.z);

        dd2 Hxx = sum3prod2(px0, px0, px1, px1, px2, px2);
        dd2 Hxy = sum3prod2(px0, py0, px1, py1, px2, py2);
        dd2 Hxz = sum3prod2(px0, pz0, px1, pz1, px2, pz2);
        dd2 Hyy = sum3prod2(py0, py0, py1, py1, py2, py2);
        dd2 Hyz = sum3prod2(py0, pz0, py1, pz1, py2, pz2);
        dd2 Hzz = sum3prod2(pz0, pz0, pz1, pz1, pz2, pz2);

        HsD[0][k][lx] = make_ulonglong2(Hxx.hi, Hxx.lo);
        HsD[1][k][lx] = make_ulonglong2(Hxy.hi, Hxy.lo);
        HsD[2][k][lx] = make_ulonglong2(Hxz.hi, Hxz.lo);
        HsD[3][k][lx] = make_ulonglong2(Hyy.hi, Hyy.lo);
        HsD[4][k][lx] = make_ulonglong2(Hyz.hi, Hyz.lo);
        HsD[5][k][lx] = make_ulonglong2(Hzz.hi, Hzz.lo);
        HsB[0][k][lx] = add2(add2(px0, px1), px2);
        HsB[1][k][lx] = add2(add2(py0, py1), py2);
        HsB[2][k][lx] = add2(add2(pz0, pz1), pz2);
    }
    __syncthreads();

    // Phase C1: vertical window sums via funnel splice — results come out
    // pixel-packed directly (lane0 = pixel row 2ty, lane1 = row 2ty+1).
    const int ty = threadIdx.y;
    const int tx = threadIdx.x;

    dd2 V[6];
#pragma unroll
    for (int q = 0; q < 6; q++) {
        ulonglong2 Au = HsD[q][ty][tx];
        ulonglong2 Bu = HsD[q][ty + 1][tx];
        dd2 a; a.hi = Au.x; a.lo = Au.y;
        dd2 f; f.hi = funnel2(Au.x, Bu.x); f.lo = funnel2(Au.y, Bu.y);
        dd2 b; b.hi = Bu.x; b.lo = Bu.y;
        V[q] = ddadd2(ddadd2(a, f), b);
    }
    ull Bv[3];
#pragma unroll
    for (int q = 0; q < 3; q++) {
        ull A = HsB[q][ty][tx];
        ull B = HsB[q][ty + 1][tx];
        Bv[q] = add2(add2(A, funnel2(A, B)), B);
    }

    const ull EPS2 = pack2(1e-5f, 1e-5f);
    dd2 Ga = ddaddf2(V[0], EPS2);
    dd2 Gb = V[1];
    dd2 Gc = V[2];
    dd2 Gd = ddaddf2(V[3], EPS2);
    dd2 Ge = V[4];
    dd2 Gf = ddaddf2(V[5], EPS2);
    ull Bx = Bv[0], By = Bv[1], Bz = Bv[2];

    // Phase C2: packed symmetric adjugate solve (both pixels per instruction).
    dd2 A00 = ddcof2(Gd, Gf, Ge, Ge);
    dd2 A01 = ddcof2(Gc, Ge, Gb, Gf);
    dd2 A02 = ddcof2(Gb, Ge, Gc, Gd);
    dd2 A11 = ddcof2(Ga, Gf, Gc, Gc);
    dd2 A12 = ddcof2(Gb, Gc, Ga, Ge);
    dd2 A22 = ddcof2(Ga, Gd, Gb, Gb);

    dd2 md0 = sum3dd2(ddmulf2(A00, Bx), ddmulf2(A01, By), ddmulf2(A02, Bz));
    dd2 md1 = sum3dd2(ddmulf2(A01, Bx), ddmulf2(A11, By), ddmulf2(A12, Bz));
    dd2 md2 = sum3dd2(ddmulf2(A02, Bx), ddmulf2(A12, By), ddmulf2(A22, Bz));

    ull m0p = add2(md0.hi, md0.lo);
    ull m1p = add2(md1.hi, md1.lo);
    ull m2p = add2(md2.hi, md2.lo);

    ull nnp = mul2(m0p, m0p);
    nnp = fma2(m1p, m1p, nnp);
    nnp = fma2(m2p, m2p, nnp);

    float m0_0, m0_1; unpack2(m0p, m0_0, m0_1);
    float m1_0, m1_1; unpack2(m1p, m1_0, m1_1);
    float m2_0, m2_1; unpack2(m2p, m2_0, m2_1);
    float nn0, nn1;   unpack2(nnp, nn0, nn1);

    float norm0 = sqrtf(nn0); if (norm0 == 0.0f) norm0 = 1e-4f;
    float norm1 = sqrtf(nn1); if (norm1 == 0.0f) norm1 = 1e-4f;

    const int gi = i0 + 2 * ty;
    const int gj = j0 + tx;
    size_t base = (size_t)bb * 3 * (HH * WW) + (size_t)gi * WW + gj;
    out[base]               = __fdiv_rn(-m0_0, norm0);
    out[base +     HH * WW] = __fdiv_rn(-m1_0, norm0);
    out[base + 2 * HH * WW] = __fdiv_rn(-m2_0, norm0);
    base += WW;   // next row, pixel 1
    out[base]               = __fdiv_rn(-m0_1, norm1);
    out[base +     HH * WW] = __fdiv_rn(-m1_1, norm1);
    out[base + 2 * HH * WW] = __fdiv_rn(-m2_1, norm1);
}

extern "C" void kernel_launch(void* const* d_in, const int* in_sizes, int n_in,
                              void* d_out, int out_size) {
    const float* depth = (const float*)d_in[0];
    float* out = (float*)d_out;

    rays_kernel<<<(WW + HH + 255) / 256, 256>>>();

    dim3 block(BW, TY, 1);
    dim3 grid(WW / BW, HH / TH, BATCH);
    normals_kernel<<<grid, block>>>(depth, out);
}